// round 3
// baseline (speedup 1.0000x reference)
#include <cuda_runtime.h>

// upfirdn2d(up=2, down=1, pad=5) with 12x12 separable kernel K = h h^T.
// out[oy,ox] = sum_{my,mx} h[oy+6-2my] * h[ox+6-2mx] * x[my,mx]
// Polyphase: for output o, base m0 = (o>>1) - 2, 6 taps:
//   o even: taps h[10-2t], o odd: taps h[11-2t], t=0..5, SAME inputs x[m0+t].
// => (even,odd) output pair = 6 x fma.rn.f32x2 with broadcast input.

#define IMG_H 256
#define IMG_W 256
#define OUT_H 511
#define OUT_W 511
#define TILE  64
#define IN_T  37      // input rows/cols needed per 64-wide output tile
#define SPITCH 37     // odd pitch -> conflict-free s_in reads
#define TP2   33      // float2 pitch for tmp rows (66 floats)

__device__ __forceinline__ float2 ffma2(float2 a, float2 b, float2 c) {
    float2 d;
    asm("fma.rn.f32x2 %0, %1, %2, %3;"
        : "=l"(*reinterpret_cast<unsigned long long*>(&d))
        : "l"(*reinterpret_cast<unsigned long long*>(&a)),
          "l"(*reinterpret_cast<unsigned long long*>(&b)),
          "l"(*reinterpret_cast<unsigned long long*>(&c)));
    return d;
}

__global__ __launch_bounds__(256)
void lpf_up2_kernel(const float* __restrict__ x,
                    const float* __restrict__ K,
                    float* __restrict__ out) {
    __shared__ float  s_in[IN_T * SPITCH];     // input tile (zero-padded halo)
    __shared__ float2 s_tmp[IN_T * TP2];       // horizontal result: 37 rows x 64 cols (as 32 float2)
    __shared__ float2 s_c[6];                  // (h_even_tap[t], h_odd_tap[t])

    const int tid = threadIdx.x;
    const int img = blockIdx.z;
    const int ox0 = blockIdx.x * TILE;         // even
    const int oy0 = blockIdx.y * TILE;         // even
    const int mx0 = (ox0 >> 1) - 2;
    const int my0 = (oy0 >> 1) - 2;

    // Recover separable h from K row 5: h[j] = K[5][j] / sqrt(K[5][5]).
    // Sign ambiguity cancels (all taps are h*h products).
    if (tid < 6) {
        float s = rsqrtf(K[5 * 12 + 5]);
        s_c[tid] = make_float2(K[5 * 12 + (10 - 2 * tid)] * s,
                               K[5 * 12 + (11 - 2 * tid)] * s);
    }

    // ---- Load input tile (coalesced, zero-fill out of bounds) ----
    const float* __restrict__ xin = x + (size_t)img * (IMG_H * IMG_W);
    for (int idx = tid; idx < IN_T * IN_T; idx += 256) {
        int r = idx / IN_T;
        int c = idx - r * IN_T;
        int gy = my0 + r;
        int gx = mx0 + c;
        float v = 0.0f;
        if ((unsigned)gy < IMG_H && (unsigned)gx < IMG_W)
            v = xin[gy * IMG_W + gx];
        s_in[r * SPITCH + c] = v;
    }
    __syncthreads();

    const float2 c0 = s_c[0], c1 = s_c[1], c2 = s_c[2],
                 c3 = s_c[3], c4 = s_c[4], c5 = s_c[5];

    // ---- Horizontal pass: tmp[r][2k],tmp[r][2k+1] = sum_t c[t]*s_in[r][k+t] ----
    // 37 rows x 4 groups of 8 pairs = 148 tasks; sliding 6-reg window.
    if (tid < IN_T * 4) {
        int kg = tid / IN_T;            // 0..3
        int r  = tid - kg * IN_T;       // 0..36
        int k0 = kg * 8;
        const float* row = s_in + r * SPITCH;
        float2* trow = s_tmp + r * TP2;
        float w0 = row[k0 + 0], w1 = row[k0 + 1], w2 = row[k0 + 2],
              w3 = row[k0 + 3], w4 = row[k0 + 4], w5 = row[k0 + 5];
        #pragma unroll
        for (int j = 0; j < 8; j++) {
            float2 acc = ffma2(make_float2(w0, w0), c0, make_float2(0.f, 0.f));
            acc = ffma2(make_float2(w1, w1), c1, acc);
            acc = ffma2(make_float2(w2, w2), c2, acc);
            acc = ffma2(make_float2(w3, w3), c3, acc);
            acc = ffma2(make_float2(w4, w4), c4, acc);
            acc = ffma2(make_float2(w5, w5), c5, acc);
            trow[k0 + j] = acc;
            w0 = w1; w1 = w2; w2 = w3; w3 = w4; w4 = w5;
            if (j < 7) w5 = row[k0 + j + 6];   // max col = 36
        }
    }
    __syncthreads();

    // ---- Vertical pass: out rows (2J, 2J+1) = sum_t c[t]*tmp[J+t][ox] ----
    // 64 columns x 4 groups of 8 row-pairs; sliding 6-reg window (13 LDS / 8 pairs).
    const int ox = tid & 63;
    const int j0 = (tid >> 6) * 8;      // 0,8,16,24
    const float* tf = reinterpret_cast<const float*>(s_tmp);  // row stride 66 floats
    float v0 = tf[(j0 + 0) * (TP2 * 2) + ox];
    float v1 = tf[(j0 + 1) * (TP2 * 2) + ox];
    float v2 = tf[(j0 + 2) * (TP2 * 2) + ox];
    float v3 = tf[(j0 + 3) * (TP2 * 2) + ox];
    float v4 = tf[(j0 + 4) * (TP2 * 2) + ox];
    float v5 = tf[(j0 + 5) * (TP2 * 2) + ox];

    float* __restrict__ o_img = out + (size_t)img * ((size_t)OUT_H * OUT_W);
    const int  gox = ox0 + ox;
    const bool xok = (gox < OUT_W);

    #pragma unroll
    for (int j = 0; j < 8; j++) {
        float2 acc = ffma2(make_float2(v0, v0), c0, make_float2(0.f, 0.f));
        acc = ffma2(make_float2(v1, v1), c1, acc);
        acc = ffma2(make_float2(v2, v2), c2, acc);
        acc = ffma2(make_float2(v3, v3), c3, acc);
        acc = ffma2(make_float2(v4, v4), c4, acc);
        acc = ffma2(make_float2(v5, v5), c5, acc);
        const int goy = oy0 + 2 * (j0 + j);
        if (xok) {
            o_img[(size_t)goy * OUT_W + gox] = acc.x;      // goy <= 510 always
            if (goy + 1 < OUT_H)
                o_img[(size_t)(goy + 1) * OUT_W + gox] = acc.y;
        }
        v0 = v1; v1 = v2; v2 = v3; v3 = v4; v4 = v5;
        if (j < 7) v5 = tf[(j0 + j + 6) * (TP2 * 2) + ox]; // max row = 36
    }
}

extern "C" void kernel_launch(void* const* d_in, const int* in_sizes, int n_in,
                              void* d_out, int out_size) {
    const float* x = (const float*)d_in[0];   // [8,64,256,256] f32
    const float* K = (const float*)d_in[1];   // [12,12] f32
    float* out = (float*)d_out;               // [8,64,511,511] f32

    int imgs = in_sizes[0] / (IMG_H * IMG_W); // 512
    dim3 grid((OUT_W + TILE - 1) / TILE,      // 8
              (OUT_H + TILE - 1) / TILE,      // 8
              imgs);                          // 512
    lpf_up2_kernel<<<grid, 256>>>(x, K, out);
}

// round 4
// speedup vs baseline: 1.4229x; 1.4229x over previous
#include <cuda_runtime.h>

// upfirdn2d(up=2, down=1, pad=5) with 12x12 separable kernel K = h h^T.
// Polyphase by output parity: (even,odd) output pair shares the same 6 input
// samples -> 6 x fma.rn.f32x2 with a broadcast-input pair per output pair.
// R3: broadcast pairs held in registers across the sliding window (1 pack per
// new sample instead of 2 MOVs per FFMA2) -> kill the alu-pipe bottleneck.

#define IMG_H 256
#define IMG_W 256
#define OUT_H 511
#define OUT_W 511
#define TILE  64
#define IN_T  37      // input rows/cols needed per 64-wide output tile
#define SPITCH 37     // odd pitch -> conflict-free s_in reads
#define TP2   33      // float2 pitch for tmp rows (66 floats)

__device__ __forceinline__ float2 ffma2(float2 a, float2 b, float2 c) {
    float2 d;
    asm("fma.rn.f32x2 %0, %1, %2, %3;"
        : "=l"(*reinterpret_cast<unsigned long long*>(&d))
        : "l"(*reinterpret_cast<unsigned long long*>(&a)),
          "l"(*reinterpret_cast<unsigned long long*>(&b)),
          "l"(*reinterpret_cast<unsigned long long*>(&c)));
    return d;
}

__device__ __forceinline__ float2 fmul2(float2 a, float2 b) {
    float2 d;
    asm("mul.rn.f32x2 %0, %1, %2;"
        : "=l"(*reinterpret_cast<unsigned long long*>(&d))
        : "l"(*reinterpret_cast<unsigned long long*>(&a)),
          "l"(*reinterpret_cast<unsigned long long*>(&b)));
    return d;
}

__device__ __forceinline__ float2 bcast(float w) { return make_float2(w, w); }

__global__ __launch_bounds__(256)
void lpf_up2_kernel(const float* __restrict__ x,
                    const float* __restrict__ K,
                    float* __restrict__ out) {
    __shared__ float  s_in[IN_T * SPITCH];   // input tile (zero-padded halo)
    __shared__ float2 s_tmp[IN_T * TP2];     // horizontal result: 37 rows x 32 float2
    __shared__ float2 s_c[6];                // (h_even_tap[t], h_odd_tap[t])

    const int tid = threadIdx.x;
    const int img = blockIdx.z;
    const int ox0 = blockIdx.x * TILE;       // even
    const int oy0 = blockIdx.y * TILE;       // even
    const int mx0 = (ox0 >> 1) - 2;
    const int my0 = (oy0 >> 1) - 2;

    // Recover separable h from K row 5: h[j] = K[5][j] / sqrt(K[5][5]).
    // Sign ambiguity cancels (all taps are h*h products).
    if (tid < 6) {
        float s = rsqrtf(K[5 * 12 + 5]);
        s_c[tid] = make_float2(K[5 * 12 + (10 - 2 * tid)] * s,
                               K[5 * 12 + (11 - 2 * tid)] * s);
    }

    // ---- Load input tile (coalesced, zero-fill out of bounds) ----
    const float* __restrict__ xin = x + (size_t)img * (IMG_H * IMG_W);
    #pragma unroll
    for (int idx = tid; idx < IN_T * IN_T; idx += 256) {
        int r = idx / IN_T;
        int c = idx - r * IN_T;
        int gy = my0 + r;
        int gx = mx0 + c;
        float v = 0.0f;
        if ((unsigned)gy < IMG_H && (unsigned)gx < IMG_W)
            v = xin[gy * IMG_W + gx];
        s_in[r * SPITCH + c] = v;
    }
    __syncthreads();

    const float2 c0 = s_c[0], c1 = s_c[1], c2 = s_c[2],
                 c3 = s_c[3], c4 = s_c[4], c5 = s_c[5];

    // ---- Horizontal pass: tmp[r][pair k] = sum_t c[t]*s_in[r][k+t] ----
    // 37 rows x 4 groups of 8 pairs = 148 tasks. Broadcast pairs p0..p5 live
    // in registers; one LDS + one pack per iteration.
    if (tid < IN_T * 4) {
        int kg = tid / IN_T;            // 0..3
        int r  = tid - kg * IN_T;       // 0..36
        int k0 = kg * 8;
        const float* row = s_in + r * SPITCH;
        float2* trow = s_tmp + r * TP2;
        float2 p0 = bcast(row[k0 + 0]), p1 = bcast(row[k0 + 1]),
               p2 = bcast(row[k0 + 2]), p3 = bcast(row[k0 + 3]),
               p4 = bcast(row[k0 + 4]), p5 = bcast(row[k0 + 5]);
        #pragma unroll
        for (int j = 0; j < 8; j++) {
            float2 acc = fmul2(p0, c0);
            acc = ffma2(p1, c1, acc);
            acc = ffma2(p2, c2, acc);
            acc = ffma2(p3, c3, acc);
            acc = ffma2(p4, c4, acc);
            acc = ffma2(p5, c5, acc);
            trow[k0 + j] = acc;
            p0 = p1; p1 = p2; p2 = p3; p3 = p4; p4 = p5;
            if (j < 7) p5 = bcast(row[k0 + j + 6]);   // max col = 36
        }
    }
    __syncthreads();

    // ---- Vertical pass: out rows (2J, 2J+1) = sum_t c[t]*tmp[J+t][ox] ----
    // 64 columns x 4 groups of 8 row-pairs; broadcast pairs in registers.
    const int ox = tid & 63;
    const int j0 = (tid >> 6) * 8;      // 0,8,16,24
    const float* tf = reinterpret_cast<const float*>(s_tmp);  // row stride 66
    float2 v0 = bcast(tf[(j0 + 0) * (TP2 * 2) + ox]);
    float2 v1 = bcast(tf[(j0 + 1) * (TP2 * 2) + ox]);
    float2 v2 = bcast(tf[(j0 + 2) * (TP2 * 2) + ox]);
    float2 v3 = bcast(tf[(j0 + 3) * (TP2 * 2) + ox]);
    float2 v4 = bcast(tf[(j0 + 4) * (TP2 * 2) + ox]);
    float2 v5 = bcast(tf[(j0 + 5) * (TP2 * 2) + ox]);

    float* __restrict__ o_img = out + (size_t)img * ((size_t)OUT_H * OUT_W);
    const int  gox = ox0 + ox;
    const bool xok = (gox < OUT_W);

    #pragma unroll
    for (int j = 0; j < 8; j++) {
        float2 acc = fmul2(v0, c0);
        acc = ffma2(v1, c1, acc);
        acc = ffma2(v2, c2, acc);
        acc = ffma2(v3, c3, acc);
        acc = ffma2(v4, c4, acc);
        acc = ffma2(v5, c5, acc);
        const int goy = oy0 + 2 * (j0 + j);
        if (xok) {
            o_img[(size_t)goy * OUT_W + gox] = acc.x;      // goy <= 510 always
            if (goy + 1 < OUT_H)
                o_img[(size_t)(goy + 1) * OUT_W + gox] = acc.y;
        }
        v0 = v1; v1 = v2; v2 = v3; v3 = v4; v4 = v5;
        if (j < 7) v5 = bcast(tf[(j0 + j + 6) * (TP2 * 2) + ox]); // max row 36
    }
}

extern "C" void kernel_launch(void* const* d_in, const int* in_sizes, int n_in,
                              void* d_out, int out_size) {
    const float* x = (const float*)d_in[0];   // [8,64,256,256] f32
    const float* K = (const float*)d_in[1];   // [12,12] f32
    float* out = (float*)d_out;               // [8,64,511,511] f32

    int imgs = in_sizes[0] / (IMG_H * IMG_W); // 512
    dim3 grid((OUT_W + TILE - 1) / TILE,      // 8
              (OUT_H + TILE - 1) / TILE,      // 8
              imgs);                          // 512
    lpf_up2_kernel<<<grid, 256>>>(x, K, out);
}